// round 6
// baseline (speedup 1.0000x reference)
#include <cuda_runtime.h>
#include <math.h>

#define BB 8
#define HH 128
#define WW 128
#define HW (HH*WW)

typedef unsigned long long u64;

__device__ __forceinline__ u64 pk2(float lo, float hi) {
    u64 r; asm("mov.b64 %0,{%1,%2};" : "=l"(r) : "f"(lo), "f"(hi)); return r;
}
__device__ __forceinline__ void upk2(float& lo, float& hi, u64 v) {
    asm("mov.b64 {%0,%1},%2;" : "=f"(lo), "=f"(hi) : "l"(v));
}
__device__ __forceinline__ u64 fma2(u64 a, u64 b, u64 c) {
    u64 d; asm("fma.rn.f32x2 %0,%1,%2,%3;" : "=l"(d) : "l"(a), "l"(b), "l"(c)); return d;
}

// ---------------- scratch (device globals; no runtime allocation) ----------------
__device__ float g_x1[BB*128*HW];     // conv1 out / fus conv out (64MB)
__device__ float g_x2[BB*64*HW];      // conv2 out / ce (32MB)
__device__ float g_de[BB*64*HW];      // de (32MB)
__device__ float g_cv[(size_t)BB*81*HW]; // cost volume (40.5MB)
__device__ float g_pred[BB*3*HW];
__device__ float g_valid[BB*HW];
__device__ float g_mean[5*BB*32];
__device__ float g_rstd[5*BB*32];
__device__ float g_veff[128];

// ---------------- 3x3 conv, pad=1, f32x2 packed ----------------
// 32x16 spatial tile, COUT_PB outputs per block, 128 threads.
// Each thread: 4 horizontal pixels as 2 f32x2 accumulators x COUT_PB channels.
// Shared loads are all 8B-aligned LDS.64 (row pitch 34 floats => base % 8B == 0).
// Weights staged in smem pre-duplicated as (w,w) pairs -> single broadcast LDS.64
// feeds fma.rn.f32x2 directly.
template<int CIN, int COUT_PB>
__launch_bounds__(128)
__global__ void conv3x3f2_k(const float* __restrict__ in0, const float* __restrict__ in1,
                            long bs0, long bs1,
                            const float* __restrict__ wgt,
                            float* __restrict__ out, int cout_total)
{
    constexpr int CT = 8;
    constexpr int HALF = CIN/2;
    constexpr int PITCH = 34;                   // 32 + 2 halo
    __shared__ float s_in[CT*18*PITCH];         // 19584 B
    __shared__ float s_w[COUT_PB*CT*9*2];       // duplicated pairs, <= 4608 B

    int tid = threadIdx.x;
    int tx0 = (blockIdx.x & 3) * 32, ty0 = (blockIdx.x >> 2) * 16;
    int b = blockIdx.y;
    int co0 = blockIdx.z * COUT_PB;
    int tx = tid & 7, ty = tid >> 3;            // 8 quad-pixels x 16 rows

    u64 acc[2*COUT_PB];
    #pragma unroll
    for (int i = 0; i < 2*COUT_PB; i++) acc[i] = 0ull;

    for (int c0 = 0; c0 < CIN; c0 += CT) {
        const float* inp = (c0 < HALF) ? (in0 + (long)b*bs0 + (long)c0*HW)
                                       : (in1 + (long)b*bs1 + (long)(c0-HALF)*HW);
        __syncthreads();
        // load CT channels x 18x34 window (zero-padded)
        for (int i = tid; i < CT*18*34; i += 128) {
            int ci = i / (18*34); int r = i % (18*34); int y = r / 34, x = r % 34;
            int gy = ty0 + y - 1, gx = tx0 + x - 1;
            float v = 0.f;
            if ((unsigned)gy < 128u && (unsigned)gx < 128u)
                v = inp[ci*HW + gy*WW + gx];
            s_in[(ci*18 + y)*PITCH + x] = v;
        }
        // stage weights duplicated: s_w[2i]=s_w[2i+1]=w
        for (int i = tid; i < COUT_PB*CT*9; i += 128) {
            int co = i / (CT*9); int r = i % (CT*9);
            float w = wgt[(long)(co0+co)*CIN*9 + (long)c0*9 + r];
            s_w[2*i] = w; s_w[2*i+1] = w;
        }
        __syncthreads();

        #pragma unroll 1
        for (int ci = 0; ci < CT; ci++) {
            // 6 input floats per row -> 5 overlapping f32x2 pairs (3x LDS.64 + 2 packs)
            u64 pv[3][5];
            #pragma unroll
            for (int r = 0; r < 3; r++) {
                const float* row = &s_in[(ci*18 + ty + r)*PITCH + 4*tx];
                u64 p0 = *(const u64*)(row);
                u64 p2 = *(const u64*)(row + 2);
                u64 p4 = *(const u64*)(row + 4);
                float v0, v1, v2, v3, v4, v5;
                upk2(v0, v1, p0); upk2(v2, v3, p2); upk2(v4, v5, p4);
                pv[r][0] = p0;
                pv[r][1] = pk2(v1, v2);
                pv[r][2] = p2;
                pv[r][3] = pk2(v3, v4);
                pv[r][4] = p4;
            }
            #pragma unroll
            for (int co = 0; co < COUT_PB; co++) {
                const float* wp = &s_w[(co*CT + ci)*18];
                u64 a0 = acc[2*co], a1 = acc[2*co+1];
                #pragma unroll
                for (int r = 0; r < 3; r++) {
                    #pragma unroll
                    for (int k = 0; k < 3; k++) {
                        u64 w2 = *(const u64*)(wp + (r*3+k)*2);  // broadcast LDS.64
                        a0 = fma2(w2, pv[r][k],   a0);           // pixels 0,1
                        a1 = fma2(w2, pv[r][k+2], a1);           // pixels 2,3
                    }
                }
                acc[2*co] = a0; acc[2*co+1] = a1;
            }
        }
    }
    int gy = ty0 + ty, gx = tx0 + 4*tx;
    #pragma unroll
    for (int co = 0; co < COUT_PB; co++) {
        float4 o;
        upk2(o.x, o.y, acc[2*co]);
        upk2(o.z, o.w, acc[2*co+1]);
        *(float4*)&out[(((long)b*cout_total + co0+co)*HH + gy)*WW + gx] = o;
    }
}

// ---------------- GroupNorm statistics: one block per (group, batch) ----------------
__global__ void gn_stats_k(const float* __restrict__ x, float* __restrict__ mean,
                           float* __restrict__ rstd, int cpg)
{
    int g = blockIdx.x, b = blockIdx.y;
    int n = cpg * HW;
    const float* p = x + (size_t)(b*32 + g) * n;
    float s = 0.f, s2 = 0.f;
    for (int i = threadIdx.x*4; i < n; i += blockDim.x*4) {
        float4 v = *(const float4*)(p + i);
        s  += v.x + v.y + v.z + v.w;
        s2 += v.x*v.x + v.y*v.y + v.z*v.z + v.w*v.w;
    }
    __shared__ float sh[2][32];
    int lane = threadIdx.x & 31, wid = threadIdx.x >> 5;
    #pragma unroll
    for (int o = 16; o; o >>= 1) { s += __shfl_down_sync(~0u, s, o); s2 += __shfl_down_sync(~0u, s2, o); }
    if (lane == 0) { sh[0][wid] = s; sh[1][wid] = s2; }
    __syncthreads();
    if (wid == 0) {
        int nw = blockDim.x >> 5;
        s  = (lane < nw) ? sh[0][lane] : 0.f;
        s2 = (lane < nw) ? sh[1][lane] : 0.f;
        #pragma unroll
        for (int o = 16; o; o >>= 1) { s += __shfl_down_sync(~0u, s, o); s2 += __shfl_down_sync(~0u, s2, o); }
        if (lane == 0) {
            float m = s / n;
            float var = s2 / n - m*m;
            mean[b*32+g] = m;
            rstd[b*32+g] = rsqrtf(var + 1e-5f);
        }
    }
}

// ---------------- elementwise normalize + activation (ACT 0=silu, 1=relu), in place ----------------
template<int ACT>
__global__ void norm_act_k(float* __restrict__ x, const float* __restrict__ gamma,
                           const float* __restrict__ beta, const float* __restrict__ mean,
                           const float* __restrict__ rstd, int C, int cpg)
{
    size_t i4 = (size_t)blockIdx.x*blockDim.x + threadIdx.x;
    size_t e = i4 * 4;
    size_t total = (size_t)BB * C * HW;
    if (e >= total) return;
    int c = (int)((e / HW) % C);
    int b = (int)(e / ((size_t)HW * C));
    int g = c / cpg;
    float m = mean[b*32+g], rs = rstd[b*32+g];
    float ga = gamma[c] * rs;
    float be = beta[c] - m * ga;
    float4 v = *(float4*)(x + e);
    float o[4] = {v.x, v.y, v.z, v.w};
    #pragma unroll
    for (int k = 0; k < 4; k++) {
        float y = o[k]*ga + be;
        if (ACT == 0) y = y / (1.f + expf(-y));  // silu
        else          y = fmaxf(y, 0.f);          // relu
        o[k] = y;
    }
    *(float4*)(x + e) = make_float4(o[0], o[1], o[2], o[3]);
}

// ---------------- flow + validity from pred ----------------
__global__ void flowval_k(const float* __restrict__ pred, const float* __restrict__ bias3,
                          float* __restrict__ out_flow, float* __restrict__ valid)
{
    int i = blockIdx.x*blockDim.x + threadIdx.x;
    if (i >= BB*HW) return;
    int b = i / HW, hw = i % HW;
    out_flow[(b*2+0)*HW + hw] = pred[(b*3+0)*HW + hw] + bias3[0];
    out_flow[(b*2+1)*HW + hw] = pred[(b*3+1)*HW + hw] + bias3[1];
    float z = pred[(b*3+2)*HW + hw] + bias3[2];
    valid[i] = 1.f / (1.f + expf(-z));
}

// ---------------- bilinear warp * validity ----------------
__global__ void warp_k(const float* __restrict__ feat2, const float* __restrict__ flow,
                       const float* __restrict__ valid, float* __restrict__ aligned)
{
    int i = blockIdx.x*blockDim.x + threadIdx.x;
    if (i >= BB*HW) return;
    int b = i / HW, hw = i % HW;
    int h = hw / WW, w = hw % WW;
    float px = (float)w + flow[(b*2+0)*HW + hw];
    float py = (float)h + flow[(b*2+1)*HW + hw];
    float x0f = floorf(px), y0f = floorf(py);
    float wx = px - x0f, wy = py - y0f;
    int x0 = (int)x0f, y0 = (int)y0f;
    int x1 = x0 + 1, y1 = y0 + 1;
    float m00 = (x0 >= 0 && x0 < WW && y0 >= 0 && y0 < HH) ? 1.f : 0.f;
    float m10 = (x1 >= 0 && x1 < WW && y0 >= 0 && y0 < HH) ? 1.f : 0.f;
    float m01 = (x0 >= 0 && x0 < WW && y1 >= 0 && y1 < HH) ? 1.f : 0.f;
    float m11 = (x1 >= 0 && x1 < WW && y1 >= 0 && y1 < HH) ? 1.f : 0.f;
    int xc0 = min(max(x0,0),WW-1), xc1 = min(max(x1,0),WW-1);
    int yc0 = min(max(y0,0),HH-1), yc1 = min(max(y1,0),HH-1);
    float w00 = (1.f-wx)*(1.f-wy)*m00, w10 = wx*(1.f-wy)*m10;
    float w01 = (1.f-wx)*wy*m01,       w11 = wx*wy*m11;
    float vd = valid[i];
    int o00 = yc0*WW+xc0, o10 = yc0*WW+xc1, o01 = yc1*WW+xc0, o11 = yc1*WW+xc1;
    const float* base = feat2 + (size_t)b*128*HW;
    float* obase = aligned + (size_t)b*128*HW + hw;
    #pragma unroll 4
    for (int c = 0; c < 128; c++) {
        const float* img = base + (size_t)c*HW;
        float s = img[o00]*w00 + img[o10]*w10 + img[o01]*w01 + img[o11]*w11;
        obase[(size_t)c*HW] = s * vd;
    }
}

// ---------------- cost volume: 81 displacements, mean over 128 channels ----------------
__launch_bounds__(256)
__global__ void costvol_k(const float* __restrict__ f1, const float* __restrict__ al,
                          float* __restrict__ cv)
{
    __shared__ float s[8*24*25];
    int tid = threadIdx.x;
    int tileIdx = blockIdx.x;
    int tx0 = (tileIdx & 7) * 16, ty0 = (tileIdx >> 3) * 16;
    int b = blockIdx.y;
    int tx = tid & 15, ty = tid >> 4;
    float acc[81];
    #pragma unroll
    for (int d = 0; d < 81; d++) acc[d] = 0.f;

    for (int c0 = 0; c0 < 128; c0 += 8) {
        __syncthreads();
        for (int i = tid; i < 8*24*24; i += 256) {
            int ci = i / 576, r = i % 576, y = r / 24, x = r % 24;
            int gy = ty0 + y - 4, gx = tx0 + x - 4;
            float v = 0.f;
            if ((unsigned)gy < 128u && (unsigned)gx < 128u)
                v = al[(size_t)(b*128 + c0 + ci)*HW + gy*WW + gx];
            s[(ci*24 + y)*25 + x] = v;
        }
        __syncthreads();
        #pragma unroll 1
        for (int ci = 0; ci < 8; ci++) {
            float f = f1[(size_t)(b*128 + c0 + ci)*HW + (ty0+ty)*WW + tx0+tx];
            #pragma unroll
            for (int dy = 0; dy < 9; dy++)
                #pragma unroll
                for (int dx = 0; dx < 9; dx++)
                    acc[dy*9+dx] = fmaf(f, s[(ci*24 + ty + dy)*25 + tx + dx], acc[dy*9+dx]);
        }
    }
    const float inv = 1.f / 128.f;
    int off = (ty0+ty)*WW + tx0+tx;
    #pragma unroll 1
    for (int d = 0; d < 81; d++)
        cv[(size_t)(b*81 + d)*HW + off] = acc[d] * inv;
}

// ---------------- 1x1 conv (MODE 0: plain read; MODE 1: |inA - inB| on the fly) ----------------
template<int CIN, int COUT, int MODE>
__launch_bounds__(128)
__global__ void conv1x1_k(const float* __restrict__ inA, const float* __restrict__ inB,
                          const float* __restrict__ wgt, float* __restrict__ out)
{
    __shared__ float s_w[COUT*CIN];
    for (int i = threadIdx.x; i < COUT*CIN; i += 128) s_w[i] = wgt[i];
    __syncthreads();
    int p = blockIdx.x*128 + threadIdx.x;
    int b = p / HW, hw = p % HW;
    float acc[COUT];
    #pragma unroll
    for (int co = 0; co < COUT; co++) acc[co] = 0.f;
    #pragma unroll 1
    for (int ci = 0; ci < CIN; ci++) {
        float v;
        if (MODE == 1) {
            size_t idx = (size_t)(b*128 + ci)*HW + hw;
            v = fabsf(inA[idx] - inB[idx]);
        } else {
            v = inA[(size_t)(b*CIN + ci)*HW + hw];
        }
        #pragma unroll
        for (int co = 0; co < COUT; co++)
            acc[co] = fmaf(s_w[co*CIN + ci], v, acc[co]);
    }
    #pragma unroll 1
    for (int co = 0; co < COUT; co++)
        out[(size_t)(b*COUT + co)*HW + hw] = acc[co];
}

// ---------------- effective lam weight: veff[ci] = sum_co lam_w[co] * fus_w2[co][ci] ----------------
__global__ void lam_eff_k(const float* __restrict__ lam_w, const float* __restrict__ fus_w2,
                          float* __restrict__ veff)
{
    int ci = threadIdx.x;
    float a = 0.f;
    for (int co = 0; co < 128; co++)
        a = fmaf(lam_w[co], fus_w2[co*128 + ci], a);
    veff[ci] = a;
}

// ---------------- final: GN(fus)->relu -> dot(veff) -> sigmoid ----------------
__global__ void lam_final_k(const float* __restrict__ fbuf, const float* __restrict__ gamma,
                            const float* __restrict__ beta, const float* __restrict__ mean,
                            const float* __restrict__ rstd, const float* __restrict__ veff,
                            const float* __restrict__ lam_b, float* __restrict__ out_lam)
{
    __shared__ float sg[128], sb[128], sv[128];
    for (int i = threadIdx.x; i < 128; i += blockDim.x) {
        sg[i] = gamma[i]; sb[i] = beta[i]; sv[i] = veff[i];
    }
    __syncthreads();
    int p = blockIdx.x*blockDim.x + threadIdx.x;
    if (p >= BB*HW) return;
    int b = p / HW, hw = p % HW;
    float a = lam_b[0];
    const float* fb = fbuf + (size_t)b*128*HW + hw;
    const float* mp = mean + b*32;
    const float* rp = rstd + b*32;
    #pragma unroll 4
    for (int ci = 0; ci < 128; ci++) {
        float x = fb[(size_t)ci*HW];
        int g = ci >> 2;
        float y = (x - mp[g]) * rp[g] * sg[ci] + sb[ci];
        a = fmaf(fmaxf(y, 0.f), sv[ci], a);
    }
    out_lam[p] = 1.f / (1.f + expf(-a));
}

// ---------------- launch ----------------
extern "C" void kernel_launch(void* const* d_in, const int* in_sizes, int n_in,
                              void* d_out, int out_size)
{
    const float* feat1     = (const float*)d_in[0];
    const float* feat2     = (const float*)d_in[1];
    const float* off_w1    = (const float*)d_in[2];
    const float* off_g1    = (const float*)d_in[3];
    const float* off_b1    = (const float*)d_in[4];
    const float* off_w2    = (const float*)d_in[5];
    const float* off_g2    = (const float*)d_in[6];
    const float* off_b2    = (const float*)d_in[7];
    const float* off_w3    = (const float*)d_in[8];
    const float* off_bias3 = (const float*)d_in[9];
    const float* corr_w    = (const float*)d_in[10];
    const float* corr_g    = (const float*)d_in[11];
    const float* corr_b    = (const float*)d_in[12];
    const float* diff_w    = (const float*)d_in[13];
    const float* diff_g    = (const float*)d_in[14];
    const float* diff_b    = (const float*)d_in[15];
    const float* fus_w1    = (const float*)d_in[16];
    const float* fus_g1    = (const float*)d_in[17];
    const float* fus_b1    = (const float*)d_in[18];
    const float* fus_w2    = (const float*)d_in[19];
    const float* lam_w     = (const float*)d_in[20];
    const float* lam_b     = (const float*)d_in[21];

    float *x1, *x2, *de, *cv, *pred, *valid, *mean, *rstd, *veff;
    cudaGetSymbolAddress((void**)&x1,    g_x1);
    cudaGetSymbolAddress((void**)&x2,    g_x2);
    cudaGetSymbolAddress((void**)&de,    g_de);
    cudaGetSymbolAddress((void**)&cv,    g_cv);
    cudaGetSymbolAddress((void**)&pred,  g_pred);
    cudaGetSymbolAddress((void**)&valid, g_valid);
    cudaGetSymbolAddress((void**)&mean,  g_mean);
    cudaGetSymbolAddress((void**)&rstd,  g_rstd);
    cudaGetSymbolAddress((void**)&veff,  g_veff);

    float* out_aligned = (float*)d_out;
    float* out_flow    = out_aligned + (size_t)BB*128*HW;
    float* out_lam     = out_flow    + (size_t)BB*2*HW;

    float* mean0 = mean;          float* rstd0 = rstd;
    float* mean1 = mean + 256;    float* rstd1 = rstd + 256;
    float* mean2 = mean + 512;    float* rstd2 = rstd + 512;
    float* mean3 = mean + 768;    float* rstd3 = rstd + 768;
    float* mean4 = mean + 1024;   float* rstd4 = rstd + 1024;

    const long BS128 = (long)128*HW;
    const long BS64  = (long)64*HW;

    // offset head: conv1 (concat feat1|feat2) -> GN -> silu
    conv3x3f2_k<256,8><<<dim3(32,BB,16),128>>>(feat1, feat2, BS128, BS128, off_w1, x1, 128);
    gn_stats_k<<<dim3(32,BB),256>>>(x1, mean0, rstd0, 4);
    norm_act_k<0><<<(BB*128*HW/4+255)/256,256>>>(x1, off_g1, off_b1, mean0, rstd0, 128, 4);

    // conv2 -> GN -> silu
    conv3x3f2_k<128,8><<<dim3(32,BB,8),128>>>(x1, x1 + 64*HW, BS128, BS128, off_w2, x2, 64);
    gn_stats_k<<<dim3(32,BB),256>>>(x2, mean1, rstd1, 2);
    norm_act_k<0><<<(BB*64*HW/4+255)/256,256>>>(x2, off_g2, off_b2, mean1, rstd1, 64, 2);

    // conv3 -> pred; flow + validity
    conv3x3f2_k<64,3><<<dim3(32,BB,1),128>>>(x2, x2 + 32*HW, BS64, BS64, off_w3, pred, 3);
    flowval_k<<<(BB*HW+255)/256,256>>>(pred, off_bias3, out_flow, valid);

    // bilinear warp * validity -> aligned (directly into d_out)
    warp_k<<<(BB*HW+255)/256,256>>>(feat2, out_flow, valid, out_aligned);

    // cost volume
    costvol_k<<<dim3(64,BB),256>>>(feat1, out_aligned, cv);

    // corr branch: 1x1(81->64) -> GN -> relu   (ce reuses x2)
    conv1x1_k<81,64,0><<<BB*HW/128,128>>>(cv, nullptr, corr_w, x2);
    gn_stats_k<<<dim3(32,BB),256>>>(x2, mean2, rstd2, 2);
    norm_act_k<1><<<(BB*64*HW/4+255)/256,256>>>(x2, corr_g, corr_b, mean2, rstd2, 64, 2);

    // diff branch: |feat1-aligned| fused into 1x1(128->64) -> GN -> relu
    conv1x1_k<128,64,1><<<BB*HW/128,128>>>(feat1, out_aligned, diff_w, de);
    gn_stats_k<<<dim3(32,BB),256>>>(de, mean3, rstd3, 2);
    norm_act_k<1><<<(BB*64*HW/4+255)/256,256>>>(de, diff_g, diff_b, mean3, rstd3, 64, 2);

    // fusion conv3x3 (concat ce|de) -> GN stats (norm fused into final)
    conv3x3f2_k<128,8><<<dim3(32,BB,16),128>>>(x2, de, BS64, BS64, fus_w1, x1, 128);
    gn_stats_k<<<dim3(32,BB),256>>>(x1, mean4, rstd4, 4);

    // lam: veff = lam_w @ fus_w2, then per-pixel dot + sigmoid
    lam_eff_k<<<1,128>>>(lam_w, fus_w2, veff);
    lam_final_k<<<(BB*HW+255)/256,256>>>(x1, fus_g1, fus_b1, mean4, rstd4, veff, lam_b, out_lam);
}

// round 9
// speedup vs baseline: 1.2714x; 1.2714x over previous
#include <cuda_runtime.h>
#include <math.h>

#define BB 8
#define HH 128
#define WW 128
#define HW (HH*WW)

typedef unsigned long long u64;

__device__ __forceinline__ u64 pk2(float lo, float hi) {
    u64 r; asm("mov.b64 %0,{%1,%2};" : "=l"(r) : "f"(lo), "f"(hi)); return r;
}
__device__ __forceinline__ void upk2(float& lo, float& hi, u64 v) {
    asm("mov.b64 {%0,%1},%2;" : "=f"(lo), "=f"(hi) : "l"(v));
}
__device__ __forceinline__ u64 fma2(u64 a, u64 b, u64 c) {
    u64 d; asm("fma.rn.f32x2 %0,%1,%2,%3;" : "=l"(d) : "l"(a), "l"(b), "l"(c)); return d;
}

// ---------------- scratch (device globals; no runtime allocation) ----------------
__device__ float g_x1[BB*128*HW];     // conv1 out / fus conv out (64MB)
__device__ float g_x2[BB*64*HW];      // conv2 out / ce (32MB)
__device__ float g_de[BB*64*HW];      // de (32MB)
__device__ float g_cv[(size_t)BB*81*HW]; // cost volume (40.5MB)
__device__ float g_pred[BB*3*HW];
__device__ float g_valid[BB*HW];
__device__ float g_mean[5*BB*32];
__device__ float g_rstd[5*BB*32];
__device__ float g_veff[128];

// ---------------- 3x3 conv, pad=1, f32x2 packed, 8 px/thread ----------------
// 64x16 spatial tile, 128 threads, each thread computes 8 horizontal pixels
// (4 f32x2 accumulator pairs) x COUT_PB out-channels. One broadcast weight
// LDS.64 feeds 4 FMA2 -> fma-pipe bound. Window loader precomputes indices
// once per chunk (no per-element div/mod).
template<int CIN, int COUT_PB>
__launch_bounds__(128)
__global__ void conv3x3v2_k(const float* __restrict__ in0, const float* __restrict__ in1,
                            long bs0, long bs1,
                            const float* __restrict__ wgt,
                            float* __restrict__ out, int cout_total)
{
    constexpr int CT = 8;
    constexpr int HALF = CIN/2;
    constexpr int WC = 66, WR = 18;             // window 18 rows x 66 cols
    constexpr int WPOS = WR*WC;                 // 1188 spatial positions
    __shared__ float s_in[CT*WPOS];             // 38016 B
    __shared__ float s_w[COUT_PB*CT*9*2];       // duplicated (w,w) pairs

    int tid = threadIdx.x;
    int tx0 = (blockIdx.x & 1) * 64, ty0 = (blockIdx.x >> 1) * 16;
    int b = blockIdx.y;
    int co0 = blockIdx.z * COUT_PB;
    int tx = tid & 7, ty = tid >> 3;            // 8 groups of 8px x 16 rows

    u64 acc[4*COUT_PB];
    #pragma unroll
    for (int i = 0; i < 4*COUT_PB; i++) acc[i] = 0ull;

    for (int c0 = 0; c0 < CIN; c0 += CT) {
        const float* inp = (c0 < HALF) ? (in0 + (long)b*bs0 + (long)c0*HW)
                                       : (in1 + (long)b*bs1 + (long)(c0-HALF)*HW);
        __syncthreads();
        // window load: index math once per j, pure LDG+STS inside ci loop
        #pragma unroll
        for (int j = 0; j < 10; j++) {
            int pos = tid + 128*j;
            if (pos < WPOS) {
                int y = pos / WC, x = pos - y*WC;
                int gy = ty0 + y - 1, gx = tx0 + x - 1;
                bool ok = ((unsigned)gy < 128u) && ((unsigned)gx < 128u);
                const float* gp = inp + gy*WW + gx;
                float* sp = &s_in[pos];
                #pragma unroll
                for (int ci = 0; ci < CT; ci++) {
                    float v = ok ? gp[ci*HW] : 0.f;
                    sp[ci*WPOS] = v;
                }
            }
        }
        // stage weights duplicated: s_w[2i]=s_w[2i+1]=w
        for (int i = tid; i < COUT_PB*CT*9; i += 128) {
            int co = i / (CT*9); int r = i % (CT*9);
            float w = wgt[(long)(co0+co)*CIN*9 + (long)c0*9 + r];
            s_w[2*i] = w; s_w[2*i+1] = w;
        }
        __syncthreads();

        #pragma unroll 1
        for (int ci = 0; ci < CT; ci++) {
            #pragma unroll
            for (int r = 0; r < 3; r++) {
                // 10 input floats -> 9 overlapping f32x2 pairs (5x LDS.64 + 4 packs)
                const float* row = &s_in[ci*WPOS + (ty + r)*WC + 8*tx];
                u64 pv[9];
                pv[0] = *(const u64*)(row);
                pv[2] = *(const u64*)(row + 2);
                pv[4] = *(const u64*)(row + 4);
                pv[6] = *(const u64*)(row + 6);
                pv[8] = *(const u64*)(row + 8);
                {
                    float a0,a1,b0,b1,c0f,c1,d0,d1,e0,e1;
                    upk2(a0,a1,pv[0]); upk2(b0,b1,pv[2]); upk2(c0f,c1,pv[4]);
                    upk2(d0,d1,pv[6]); upk2(e0,e1,pv[8]);
                    pv[1] = pk2(a1,b0);
                    pv[3] = pk2(b1,c0f);
                    pv[5] = pk2(c1,d0);
                    pv[7] = pk2(d1,e0);
                }
                #pragma unroll
                for (int co = 0; co < COUT_PB; co++) {
                    const float* wp = &s_w[((co*CT + ci)*9 + r*3)*2];
                    #pragma unroll
                    for (int k = 0; k < 3; k++) {
                        u64 w2 = *(const u64*)(wp + 2*k);   // broadcast LDS.64
                        acc[4*co+0] = fma2(w2, pv[k],   acc[4*co+0]);
                        acc[4*co+1] = fma2(w2, pv[k+2], acc[4*co+1]);
                        acc[4*co+2] = fma2(w2, pv[k+4], acc[4*co+2]);
                        acc[4*co+3] = fma2(w2, pv[k+6], acc[4*co+3]);
                    }
                }
            }
        }
    }
    int gy = ty0 + ty, gx = tx0 + 8*tx;
    #pragma unroll
    for (int co = 0; co < COUT_PB; co++) {
        float* op = &out[(((long)b*cout_total + co0+co)*HH + gy)*WW + gx];
        float4 o0, o1;
        upk2(o0.x, o0.y, acc[4*co+0]);
        upk2(o0.z, o0.w, acc[4*co+1]);
        upk2(o1.x, o1.y, acc[4*co+2]);
        upk2(o1.z, o1.w, acc[4*co+3]);
        *(float4*)(op)     = o0;
        *(float4*)(op + 4) = o1;
    }
}

// ---------------- GroupNorm statistics: one block per (group, batch) ----------------
__global__ void gn_stats_k(const float* __restrict__ x, float* __restrict__ mean,
                           float* __restrict__ rstd, int cpg)
{
    int g = blockIdx.x, b = blockIdx.y;
    int n = cpg * HW;
    const float* p = x + (size_t)(b*32 + g) * n;
    float s = 0.f, s2 = 0.f;
    for (int i = threadIdx.x*4; i < n; i += blockDim.x*4) {
        float4 v = *(const float4*)(p + i);
        s  += v.x + v.y + v.z + v.w;
        s2 += v.x*v.x + v.y*v.y + v.z*v.z + v.w*v.w;
    }
    __shared__ float sh[2][32];
    int lane = threadIdx.x & 31, wid = threadIdx.x >> 5;
    #pragma unroll
    for (int o = 16; o; o >>= 1) { s += __shfl_down_sync(~0u, s, o); s2 += __shfl_down_sync(~0u, s2, o); }
    if (lane == 0) { sh[0][wid] = s; sh[1][wid] = s2; }
    __syncthreads();
    if (wid == 0) {
        int nw = blockDim.x >> 5;
        s  = (lane < nw) ? sh[0][lane] : 0.f;
        s2 = (lane < nw) ? sh[1][lane] : 0.f;
        #pragma unroll
        for (int o = 16; o; o >>= 1) { s += __shfl_down_sync(~0u, s, o); s2 += __shfl_down_sync(~0u, s2, o); }
        if (lane == 0) {
            float m = s / n;
            float var = s2 / n - m*m;
            mean[b*32+g] = m;
            rstd[b*32+g] = rsqrtf(var + 1e-5f);
        }
    }
}

// ---------------- elementwise normalize + activation (ACT 0=silu, 1=relu), in place ----------------
template<int ACT>
__global__ void norm_act_k(float* __restrict__ x, const float* __restrict__ gamma,
                           const float* __restrict__ beta, const float* __restrict__ mean,
                           const float* __restrict__ rstd, int C, int cpg)
{
    size_t i4 = (size_t)blockIdx.x*blockDim.x + threadIdx.x;
    size_t e = i4 * 4;
    size_t total = (size_t)BB * C * HW;
    if (e >= total) return;
    int c = (int)((e / HW) % C);
    int b = (int)(e / ((size_t)HW * C));
    int g = c / cpg;
    float m = mean[b*32+g], rs = rstd[b*32+g];
    float ga = gamma[c] * rs;
    float be = beta[c] - m * ga;
    float4 v = *(float4*)(x + e);
    float o[4] = {v.x, v.y, v.z, v.w};
    #pragma unroll
    for (int k = 0; k < 4; k++) {
        float y = o[k]*ga + be;
        if (ACT == 0) y = y / (1.f + expf(-y));  // silu
        else          y = fmaxf(y, 0.f);          // relu
        o[k] = y;
    }
    *(float4*)(x + e) = make_float4(o[0], o[1], o[2], o[3]);
}

// ---------------- flow + validity from pred ----------------
__global__ void flowval_k(const float* __restrict__ pred, const float* __restrict__ bias3,
                          float* __restrict__ out_flow, float* __restrict__ valid)
{
    int i = blockIdx.x*blockDim.x + threadIdx.x;
    if (i >= BB*HW) return;
    int b = i / HW, hw = i % HW;
    out_flow[(b*2+0)*HW + hw] = pred[(b*3+0)*HW + hw] + bias3[0];
    out_flow[(b*2+1)*HW + hw] = pred[(b*3+1)*HW + hw] + bias3[1];
    float z = pred[(b*3+2)*HW + hw] + bias3[2];
    valid[i] = 1.f / (1.f + expf(-z));
}

// ---------------- bilinear warp * validity ----------------
__global__ void warp_k(const float* __restrict__ feat2, const float* __restrict__ flow,
                       const float* __restrict__ valid, float* __restrict__ aligned)
{
    int i = blockIdx.x*blockDim.x + threadIdx.x;
    if (i >= BB*HW) return;
    int b = i / HW, hw = i % HW;
    int h = hw / WW, w = hw % WW;
    float px = (float)w + flow[(b*2+0)*HW + hw];
    float py = (float)h + flow[(b*2+1)*HW + hw];
    float x0f = floorf(px), y0f = floorf(py);
    float wx = px - x0f, wy = py - y0f;
    int x0 = (int)x0f, y0 = (int)y0f;
    int x1 = x0 + 1, y1 = y0 + 1;
    float m00 = (x0 >= 0 && x0 < WW && y0 >= 0 && y0 < HH) ? 1.f : 0.f;
    float m10 = (x1 >= 0 && x1 < WW && y0 >= 0 && y0 < HH) ? 1.f : 0.f;
    float m01 = (x0 >= 0 && x0 < WW && y1 >= 0 && y1 < HH) ? 1.f : 0.f;
    float m11 = (x1 >= 0 && x1 < WW && y1 >= 0 && y1 < HH) ? 1.f : 0.f;
    int xc0 = min(max(x0,0),WW-1), xc1 = min(max(x1,0),WW-1);
    int yc0 = min(max(y0,0),HH-1), yc1 = min(max(y1,0),HH-1);
    float w00 = (1.f-wx)*(1.f-wy)*m00, w10 = wx*(1.f-wy)*m10;
    float w01 = (1.f-wx)*wy*m01,       w11 = wx*wy*m11;
    float vd = valid[i];
    int o00 = yc0*WW+xc0, o10 = yc0*WW+xc1, o01 = yc1*WW+xc0, o11 = yc1*WW+xc1;
    const float* base = feat2 + (size_t)b*128*HW;
    float* obase = aligned + (size_t)b*128*HW + hw;
    #pragma unroll 4
    for (int c = 0; c < 128; c++) {
        const float* img = base + (size_t)c*HW;
        float s = img[o00]*w00 + img[o10]*w10 + img[o01]*w01 + img[o11]*w11;
        obase[(size_t)c*HW] = s * vd;
    }
}

// ---------------- cost volume: 81 displacements, mean over 128 channels ----------------
__launch_bounds__(256)
__global__ void costvol_k(const float* __restrict__ f1, const float* __restrict__ al,
                          float* __restrict__ cv)
{
    __shared__ float s[8*24*25];
    int tid = threadIdx.x;
    int tileIdx = blockIdx.x;
    int tx0 = (tileIdx & 7) * 16, ty0 = (tileIdx >> 3) * 16;
    int b = blockIdx.y;
    int tx = tid & 15, ty = tid >> 4;
    float acc[81];
    #pragma unroll
    for (int d = 0; d < 81; d++) acc[d] = 0.f;

    for (int c0 = 0; c0 < 128; c0 += 8) {
        __syncthreads();
        for (int i = tid; i < 8*24*24; i += 256) {
            int ci = i / 576, r = i % 576, y = r / 24, x = r % 24;
            int gy = ty0 + y - 4, gx = tx0 + x - 4;
            float v = 0.f;
            if ((unsigned)gy < 128u && (unsigned)gx < 128u)
                v = al[(size_t)(b*128 + c0 + ci)*HW + gy*WW + gx];
            s[(ci*24 + y)*25 + x] = v;
        }
        __syncthreads();
        #pragma unroll 1
        for (int ci = 0; ci < 8; ci++) {
            float f = f1[(size_t)(b*128 + c0 + ci)*HW + (ty0+ty)*WW + tx0+tx];
            #pragma unroll
            for (int dy = 0; dy < 9; dy++)
                #pragma unroll
                for (int dx = 0; dx < 9; dx++)
                    acc[dy*9+dx] = fmaf(f, s[(ci*24 + ty + dy)*25 + tx + dx], acc[dy*9+dx]);
        }
    }
    const float inv = 1.f / 128.f;
    int off = (ty0+ty)*WW + tx0+tx;
    #pragma unroll 1
    for (int d = 0; d < 81; d++)
        cv[(size_t)(b*81 + d)*HW + off] = acc[d] * inv;
}

// ---------------- 1x1 conv (MODE 0: plain read; MODE 1: |inA - inB| on the fly) ----------------
template<int CIN, int COUT, int MODE>
__launch_bounds__(128)
__global__ void conv1x1_k(const float* __restrict__ inA, const float* __restrict__ inB,
                          const float* __restrict__ wgt, float* __restrict__ out)
{
    __shared__ float s_w[COUT*CIN];
    for (int i = threadIdx.x; i < COUT*CIN; i += 128) s_w[i] = wgt[i];
    __syncthreads();
    int p = blockIdx.x*128 + threadIdx.x;
    int b = p / HW, hw = p % HW;
    float acc[COUT];
    #pragma unroll
    for (int co = 0; co < COUT; co++) acc[co] = 0.f;
    #pragma unroll 1
    for (int ci = 0; ci < CIN; ci++) {
        float v;
        if (MODE == 1) {
            size_t idx = (size_t)(b*128 + ci)*HW + hw;
            v = fabsf(inA[idx] - inB[idx]);
        } else {
            v = inA[(size_t)(b*CIN + ci)*HW + hw];
        }
        #pragma unroll
        for (int co = 0; co < COUT; co++)
            acc[co] = fmaf(s_w[co*CIN + ci], v, acc[co]);
    }
    #pragma unroll 1
    for (int co = 0; co < COUT; co++)
        out[(size_t)(b*COUT + co)*HW + hw] = acc[co];
}

// ---------------- effective lam weight: veff[ci] = sum_co lam_w[co] * fus_w2[co][ci] ----------------
__global__ void lam_eff_k(const float* __restrict__ lam_w, const float* __restrict__ fus_w2,
                          float* __restrict__ veff)
{
    int ci = threadIdx.x;
    float a = 0.f;
    for (int co = 0; co < 128; co++)
        a = fmaf(lam_w[co], fus_w2[co*128 + ci], a);
    veff[ci] = a;
}

// ---------------- final: GN(fus)->relu -> dot(veff) -> sigmoid ----------------
__global__ void lam_final_k(const float* __restrict__ fbuf, const float* __restrict__ gamma,
                            const float* __restrict__ beta, const float* __restrict__ mean,
                            const float* __restrict__ rstd, const float* __restrict__ veff,
                            const float* __restrict__ lam_b, float* __restrict__ out_lam)
{
    __shared__ float sg[128], sb[128], sv[128];
    for (int i = threadIdx.x; i < 128; i += blockDim.x) {
        sg[i] = gamma[i]; sb[i] = beta[i]; sv[i] = veff[i];
    }
    __syncthreads();
    int p = blockIdx.x*blockDim.x + threadIdx.x;
    if (p >= BB*HW) return;
    int b = p / HW, hw = p % HW;
    float a = lam_b[0];
    const float* fb = fbuf + (size_t)b*128*HW + hw;
    const float* mp = mean + b*32;
    const float* rp = rstd + b*32;
    #pragma unroll 4
    for (int ci = 0; ci < 128; ci++) {
        float x = fb[(size_t)ci*HW];
        int g = ci >> 2;
        float y = (x - mp[g]) * rp[g] * sg[ci] + sb[ci];
        a = fmaf(fmaxf(y, 0.f), sv[ci], a);
    }
    out_lam[p] = 1.f / (1.f + expf(-a));
}

// ---------------- launch ----------------
extern "C" void kernel_launch(void* const* d_in, const int* in_sizes, int n_in,
                              void* d_out, int out_size)
{
    const float* feat1     = (const float*)d_in[0];
    const float* feat2     = (const float*)d_in[1];
    const float* off_w1    = (const float*)d_in[2];
    const float* off_g1    = (const float*)d_in[3];
    const float* off_b1    = (const float*)d_in[4];
    const float* off_w2    = (const float*)d_in[5];
    const float* off_g2    = (const float*)d_in[6];
    const float* off_b2    = (const float*)d_in[7];
    const float* off_w3    = (const float*)d_in[8];
    const float* off_bias3 = (const float*)d_in[9];
    const float* corr_w    = (const float*)d_in[10];
    const float* corr_g    = (const float*)d_in[11];
    const float* corr_b    = (const float*)d_in[12];
    const float* diff_w    = (const float*)d_in[13];
    const float* diff_g    = (const float*)d_in[14];
    const float* diff_b    = (const float*)d_in[15];
    const float* fus_w1    = (const float*)d_in[16];
    const float* fus_g1    = (const float*)d_in[17];
    const float* fus_b1    = (const float*)d_in[18];
    const float* fus_w2    = (const float*)d_in[19];
    const float* lam_w     = (const float*)d_in[20];
    const float* lam_b     = (const float*)d_in[21];

    float *x1, *x2, *de, *cv, *pred, *valid, *mean, *rstd, *veff;
    cudaGetSymbolAddress((void**)&x1,    g_x1);
    cudaGetSymbolAddress((void**)&x2,    g_x2);
    cudaGetSymbolAddress((void**)&de,    g_de);
    cudaGetSymbolAddress((void**)&cv,    g_cv);
    cudaGetSymbolAddress((void**)&pred,  g_pred);
    cudaGetSymbolAddress((void**)&valid, g_valid);
    cudaGetSymbolAddress((void**)&mean,  g_mean);
    cudaGetSymbolAddress((void**)&rstd,  g_rstd);
    cudaGetSymbolAddress((void**)&veff,  g_veff);

    float* out_aligned = (float*)d_out;
    float* out_flow    = out_aligned + (size_t)BB*128*HW;
    float* out_lam     = out_flow    + (size_t)BB*2*HW;

    float* mean0 = mean;          float* rstd0 = rstd;
    float* mean1 = mean + 256;    float* rstd1 = rstd + 256;
    float* mean2 = mean + 512;    float* rstd2 = rstd + 512;
    float* mean3 = mean + 768;    float* rstd3 = rstd + 768;
    float* mean4 = mean + 1024;   float* rstd4 = rstd + 1024;

    const long BS128 = (long)128*HW;
    const long BS64  = (long)64*HW;

    // offset head: conv1 (concat feat1|feat2) -> GN -> silu
    conv3x3v2_k<256,8><<<dim3(16,BB,16),128>>>(feat1, feat2, BS128, BS128, off_w1, x1, 128);
    gn_stats_k<<<dim3(32,BB),256>>>(x1, mean0, rstd0, 4);
    norm_act_k<0><<<(BB*128*HW/4+255)/256,256>>>(x1, off_g1, off_b1, mean0, rstd0, 128, 4);

    // conv2 -> GN -> silu
    conv3x3v2_k<128,8><<<dim3(16,BB,8),128>>>(x1, x1 + 64*HW, BS128, BS128, off_w2, x2, 64);
    gn_stats_k<<<dim3(32,BB),256>>>(x2, mean1, rstd1, 2);
    norm_act_k<0><<<(BB*64*HW/4+255)/256,256>>>(x2, off_g2, off_b2, mean1, rstd1, 64, 2);

    // conv3 -> pred; flow + validity
    conv3x3v2_k<64,3><<<dim3(16,BB,1),128>>>(x2, x2 + 32*HW, BS64, BS64, off_w3, pred, 3);
    flowval_k<<<(BB*HW+255)/256,256>>>(pred, off_bias3, out_flow, valid);

    // bilinear warp * validity -> aligned (directly into d_out)
    warp_k<<<(BB*HW+255)/256,256>>>(feat2, out_flow, valid, out_aligned);

    // cost volume
    costvol_k<<<dim3(64,BB),256>>>(feat1, out_aligned, cv);

    // corr branch: 1x1(81->64) -> GN -> relu   (ce reuses x2)
    conv1x1_k<81,64,0><<<BB*HW/128,128>>>(cv, nullptr, corr_w, x2);
    gn_stats_k<<<dim3(32,BB),256>>>(x2, mean2, rstd2, 2);
    norm_act_k<1><<<(BB*64*HW/4+255)/256,256>>>(x2, corr_g, corr_b, mean2, rstd2, 64, 2);

    // diff branch: |feat1-aligned| fused into 1x1(128->64) -> GN -> relu
    conv1x1_k<128,64,1><<<BB*HW/128,128>>>(feat1, out_aligned, diff_w, de);
    gn_stats_k<<<dim3(32,BB),256>>>(de, mean3, rstd3, 2);
    norm_act_k<1><<<(BB*64*HW/4+255)/256,256>>>(de, diff_g, diff_b, mean3, rstd3, 64, 2);

    // fusion conv3x3 (concat ce|de) -> GN stats (norm fused into final)
    conv3x3v2_k<128,8><<<dim3(16,BB,16),128>>>(x2, de, BS64, BS64, fus_w1, x1, 128);
    gn_stats_k<<<dim3(32,BB),256>>>(x1, mean4, rstd4, 4);

    // lam: veff = lam_w @ fus_w2, then per-pixel dot + sigmoid
    lam_eff_k<<<1,128>>>(lam_w, fus_w2, veff);
    lam_final_k<<<(BB*HW+255)/256,256>>>(x1, fus_g1, fus_b1, mean4, rstd4, veff, lam_b, out_lam);
}

// round 10
// speedup vs baseline: 1.2874x; 1.0126x over previous
#include <cuda_runtime.h>
#include <math.h>

#define BB 8
#define HH 128
#define WW 128
#define HW (HH*WW)

typedef unsigned long long u64;

__device__ __forceinline__ u64 pk2(float lo, float hi) {
    u64 r; asm("mov.b64 %0,{%1,%2};" : "=l"(r) : "f"(lo), "f"(hi)); return r;
}
__device__ __forceinline__ void upk2(float& lo, float& hi, u64 v) {
    asm("mov.b64 {%0,%1},%2;" : "=f"(lo), "=f"(hi) : "l"(v));
}
__device__ __forceinline__ u64 fma2(u64 a, u64 b, u64 c) {
    u64 d; asm("fma.rn.f32x2 %0,%1,%2,%3;" : "=l"(d) : "l"(a), "l"(b), "l"(c)); return d;
}

// ---------------- scratch (device globals; no runtime allocation) ----------------
__device__ float g_x1[BB*128*HW];     // conv1 out / fus conv out (64MB)
__device__ float g_x2[BB*64*HW];      // conv2 out / ce (32MB)
__device__ float g_de[BB*64*HW];      // de (32MB)
__device__ float g_cv[(size_t)BB*81*HW]; // cost volume (40.5MB)
__device__ float g_pred[BB*3*HW];
__device__ float g_valid[BB*HW];
__device__ float g_mean[5*BB*32];
__device__ float g_rstd[5*BB*32];
__device__ float g_veff[128];

// ---------------- 3x3 conv, pad=1, f32x2 packed, 8 px/thread ----------------
// 64x16 spatial tile, 128 threads, each thread computes 8 horizontal pixels
// (4 f32x2 accumulator pairs) x COUT_PB out-channels. Weight LDS.64 batched
// 3-at-a-time ahead of 12 FMA2s. minBlocks=4 caps regs at 128 so 4 blocks/SM
// co-reside (spills, if any, confined to the once-per-chunk window loader).
template<int CIN, int COUT_PB>
__launch_bounds__(128, 4)
__global__ void conv3x3v2_k(const float* __restrict__ in0, const float* __restrict__ in1,
                            long bs0, long bs1,
                            const float* __restrict__ wgt,
                            float* __restrict__ out, int cout_total)
{
    constexpr int CT = 8;
    constexpr int HALF = CIN/2;
    constexpr int WC = 66, WR = 18;             // window 18 rows x 66 cols
    constexpr int WPOS = WR*WC;                 // 1188 spatial positions
    __shared__ float s_in[CT*WPOS];             // 38016 B
    __shared__ float s_w[COUT_PB*CT*9*2];       // duplicated (w,w) pairs

    int tid = threadIdx.x;
    int tx0 = (blockIdx.x & 1) * 64, ty0 = (blockIdx.x >> 1) * 16;
    int b = blockIdx.y;
    int co0 = blockIdx.z * COUT_PB;
    int tx = tid & 7, ty = tid >> 3;            // 8 groups of 8px x 16 rows

    u64 acc[4*COUT_PB];
    #pragma unroll
    for (int i = 0; i < 4*COUT_PB; i++) acc[i] = 0ull;

    for (int c0 = 0; c0 < CIN; c0 += CT) {
        const float* inp = (c0 < HALF) ? (in0 + (long)b*bs0 + (long)c0*HW)
                                       : (in1 + (long)b*bs1 + (long)(c0-HALF)*HW);
        __syncthreads();
        // window load: index math once per j, pure LDG+STS inside ci loop
        #pragma unroll
        for (int j = 0; j < 10; j++) {
            int pos = tid + 128*j;
            if (pos < WPOS) {
                int y = pos / WC, x = pos - y*WC;
                int gy = ty0 + y - 1, gx = tx0 + x - 1;
                bool ok = ((unsigned)gy < 128u) && ((unsigned)gx < 128u);
                const float* gp = inp + gy*WW + gx;
                float* sp = &s_in[pos];
                #pragma unroll
                for (int ci = 0; ci < CT; ci++) {
                    float v = ok ? gp[ci*HW] : 0.f;
                    sp[ci*WPOS] = v;
                }
            }
        }
        // stage weights duplicated: s_w[2i]=s_w[2i+1]=w
        for (int i = tid; i < COUT_PB*CT*9; i += 128) {
            int co = i / (CT*9); int r = i % (CT*9);
            float w = wgt[(long)(co0+co)*CIN*9 + (long)c0*9 + r];
            s_w[2*i] = w; s_w[2*i+1] = w;
        }
        __syncthreads();

        #pragma unroll 1
        for (int ci = 0; ci < CT; ci++) {
            #pragma unroll
            for (int r = 0; r < 3; r++) {
                // 10 input floats -> 9 overlapping f32x2 pairs (5x LDS.64 + 4 packs)
                const float* row = &s_in[ci*WPOS + (ty + r)*WC + 8*tx];
                u64 pv[9];
                pv[0] = *(const u64*)(row);
                pv[2] = *(const u64*)(row + 2);
                pv[4] = *(const u64*)(row + 4);
                pv[6] = *(const u64*)(row + 6);
                pv[8] = *(const u64*)(row + 8);
                {
                    float a0,a1,b0,b1,c0f,c1,d0,d1,e0,e1;
                    upk2(a0,a1,pv[0]); upk2(b0,b1,pv[2]); upk2(c0f,c1,pv[4]);
                    upk2(d0,d1,pv[6]); upk2(e0,e1,pv[8]);
                    pv[1] = pk2(a1,b0);
                    pv[3] = pk2(b1,c0f);
                    pv[5] = pk2(c1,d0);
                    pv[7] = pk2(d1,e0);
                }
                #pragma unroll
                for (int co = 0; co < COUT_PB; co++) {
                    const float* wp = &s_w[((co*CT + ci)*9 + r*3)*2];
                    // batch all 3 tap weights: 3 outstanding LDS.64, then 12 FMA2
                    u64 w0 = *(const u64*)(wp);
                    u64 w1 = *(const u64*)(wp + 2);
                    u64 w2 = *(const u64*)(wp + 4);
                    acc[4*co+0] = fma2(w0, pv[0], acc[4*co+0]);
                    acc[4*co+1] = fma2(w0, pv[2], acc[4*co+1]);
                    acc[4*co+2] = fma2(w0, pv[4], acc[4*co+2]);
                    acc[4*co+3] = fma2(w0, pv[6], acc[4*co+3]);
                    acc[4*co+0] = fma2(w1, pv[1], acc[4*co+0]);
                    acc[4*co+1] = fma2(w1, pv[3], acc[4*co+1]);
                    acc[4*co+2] = fma2(w1, pv[5], acc[4*co+2]);
                    acc[4*co+3] = fma2(w1, pv[7], acc[4*co+3]);
                    acc[4*co+0] = fma2(w2, pv[2], acc[4*co+0]);
                    acc[4*co+1] = fma2(w2, pv[4], acc[4*co+1]);
                    acc[4*co+2] = fma2(w2, pv[6], acc[4*co+2]);
                    acc[4*co+3] = fma2(w2, pv[8], acc[4*co+3]);
                }
            }
        }
    }
    int gy = ty0 + ty, gx = tx0 + 8*tx;
    #pragma unroll
    for (int co = 0; co < COUT_PB; co++) {
        float* op = &out[(((long)b*cout_total + co0+co)*HH + gy)*WW + gx];
        float4 o0, o1;
        upk2(o0.x, o0.y, acc[4*co+0]);
        upk2(o0.z, o0.w, acc[4*co+1]);
        upk2(o1.x, o1.y, acc[4*co+2]);
        upk2(o1.z, o1.w, acc[4*co+3]);
        *(float4*)(op)     = o0;
        *(float4*)(op + 4) = o1;
    }
}

// ---------------- GroupNorm statistics: one block per (group, batch) ----------------
__global__ void gn_stats_k(const float* __restrict__ x, float* __restrict__ mean,
                           float* __restrict__ rstd, int cpg)
{
    int g = blockIdx.x, b = blockIdx.y;
    int n = cpg * HW;
    const float* p = x + (size_t)(b*32 + g) * n;
    float s = 0.f, s2 = 0.f;
    for (int i = threadIdx.x*4; i < n; i += blockDim.x*4) {
        float4 v = *(const float4*)(p + i);
        s  += v.x + v.y + v.z + v.w;
        s2 += v.x*v.x + v.y*v.y + v.z*v.z + v.w*v.w;
    }
    __shared__ float sh[2][32];
    int lane = threadIdx.x & 31, wid = threadIdx.x >> 5;
    #pragma unroll
    for (int o = 16; o; o >>= 1) { s += __shfl_down_sync(~0u, s, o); s2 += __shfl_down_sync(~0u, s2, o); }
    if (lane == 0) { sh[0][wid] = s; sh[1][wid] = s2; }
    __syncthreads();
    if (wid == 0) {
        int nw = blockDim.x >> 5;
        s  = (lane < nw) ? sh[0][lane] : 0.f;
        s2 = (lane < nw) ? sh[1][lane] : 0.f;
        #pragma unroll
        for (int o = 16; o; o >>= 1) { s += __shfl_down_sync(~0u, s, o); s2 += __shfl_down_sync(~0u, s2, o); }
        if (lane == 0) {
            float m = s / n;
            float var = s2 / n - m*m;
            mean[b*32+g] = m;
            rstd[b*32+g] = rsqrtf(var + 1e-5f);
        }
    }
}

// ---------------- elementwise normalize + activation (ACT 0=silu, 1=relu), in place ----------------
template<int ACT>
__global__ void norm_act_k(float* __restrict__ x, const float* __restrict__ gamma,
                           const float* __restrict__ beta, const float* __restrict__ mean,
                           const float* __restrict__ rstd, int C, int cpg)
{
    size_t i4 = (size_t)blockIdx.x*blockDim.x + threadIdx.x;
    size_t e = i4 * 4;
    size_t total = (size_t)BB * C * HW;
    if (e >= total) return;
    int c = (int)((e / HW) % C);
    int b = (int)(e / ((size_t)HW * C));
    int g = c / cpg;
    float m = mean[b*32+g], rs = rstd[b*32+g];
    float ga = gamma[c] * rs;
    float be = beta[c] - m * ga;
    float4 v = *(float4*)(x + e);
    float o[4] = {v.x, v.y, v.z, v.w};
    #pragma unroll
    for (int k = 0; k < 4; k++) {
        float y = o[k]*ga + be;
        if (ACT == 0) y = y / (1.f + expf(-y));  // silu
        else          y = fmaxf(y, 0.f);          // relu
        o[k] = y;
    }
    *(float4*)(x + e) = make_float4(o[0], o[1], o[2], o[3]);
}

// ---------------- flow + validity from pred ----------------
__global__ void flowval_k(const float* __restrict__ pred, const float* __restrict__ bias3,
                          float* __restrict__ out_flow, float* __restrict__ valid)
{
    int i = blockIdx.x*blockDim.x + threadIdx.x;
    if (i >= BB*HW) return;
    int b = i / HW, hw = i % HW;
    out_flow[(b*2+0)*HW + hw] = pred[(b*3+0)*HW + hw] + bias3[0];
    out_flow[(b*2+1)*HW + hw] = pred[(b*3+1)*HW + hw] + bias3[1];
    float z = pred[(b*3+2)*HW + hw] + bias3[2];
    valid[i] = 1.f / (1.f + expf(-z));
}

// ---------------- bilinear warp * validity ----------------
__global__ void warp_k(const float* __restrict__ feat2, const float* __restrict__ flow,
                       const float* __restrict__ valid, float* __restrict__ aligned)
{
    int i = blockIdx.x*blockDim.x + threadIdx.x;
    if (i >= BB*HW) return;
    int b = i / HW, hw = i % HW;
    int h = hw / WW, w = hw % WW;
    float px = (float)w + flow[(b*2+0)*HW + hw];
    float py = (float)h + flow[(b*2+1)*HW + hw];
    float x0f = floorf(px), y0f = floorf(py);
    float wx = px - x0f, wy = py - y0f;
    int x0 = (int)x0f, y0 = (int)y0f;
    int x1 = x0 + 1, y1 = y0 + 1;
    float m00 = (x0 >= 0 && x0 < WW && y0 >= 0 && y0 < HH) ? 1.f : 0.f;
    float m10 = (x1 >= 0 && x1 < WW && y0 >= 0 && y0 < HH) ? 1.f : 0.f;
    float m01 = (x0 >= 0 && x0 < WW && y1 >= 0 && y1 < HH) ? 1.f : 0.f;
    float m11 = (x1 >= 0 && x1 < WW && y1 >= 0 && y1 < HH) ? 1.f : 0.f;
    int xc0 = min(max(x0,0),WW-1), xc1 = min(max(x1,0),WW-1);
    int yc0 = min(max(y0,0),HH-1), yc1 = min(max(y1,0),HH-1);
    float w00 = (1.f-wx)*(1.f-wy)*m00, w10 = wx*(1.f-wy)*m10;
    float w01 = (1.f-wx)*wy*m01,       w11 = wx*wy*m11;
    float vd = valid[i];
    int o00 = yc0*WW+xc0, o10 = yc0*WW+xc1, o01 = yc1*WW+xc0, o11 = yc1*WW+xc1;
    const float* base = feat2 + (size_t)b*128*HW;
    float* obase = aligned + (size_t)b*128*HW + hw;
    #pragma unroll 4
    for (int c = 0; c < 128; c++) {
        const float* img = base + (size_t)c*HW;
        float s = img[o00]*w00 + img[o10]*w10 + img[o01]*w01 + img[o11]*w11;
        obase[(size_t)c*HW] = s * vd;
    }
}

// ---------------- cost volume: 81 displacements, mean over 128 channels ----------------
__launch_bounds__(256)
__global__ void costvol_k(const float* __restrict__ f1, const float* __restrict__ al,
                          float* __restrict__ cv)
{
    __shared__ float s[8*24*25];
    int tid = threadIdx.x;
    int tileIdx = blockIdx.x;
    int tx0 = (tileIdx & 7) * 16, ty0 = (tileIdx >> 3) * 16;
    int b = blockIdx.y;
    int tx = tid & 15, ty = tid >> 4;
    float acc[81];
    #pragma unroll
    for (int d = 0; d < 81; d++) acc[d] = 0.f;

    for (int c0 = 0; c0 < 128; c0 += 8) {
        __syncthreads();
        for (int i = tid; i < 8*24*24; i += 256) {
            int ci = i / 576, r = i % 576, y = r / 24, x = r % 24;
            int gy = ty0 + y - 4, gx = tx0 + x - 4;
            float v = 0.f;
            if ((unsigned)gy < 128u && (unsigned)gx < 128u)
                v = al[(size_t)(b*128 + c0 + ci)*HW + gy*WW + gx];
            s[(ci*24 + y)*25 + x] = v;
        }
        __syncthreads();
        #pragma unroll 1
        for (int ci = 0; ci < 8; ci++) {
            float f = f1[(size_t)(b*128 + c0 + ci)*HW + (ty0+ty)*WW + tx0+tx];
            #pragma unroll
            for (int dy = 0; dy < 9; dy++)
                #pragma unroll
                for (int dx = 0; dx < 9; dx++)
                    acc[dy*9+dx] = fmaf(f, s[(ci*24 + ty + dy)*25 + tx + dx], acc[dy*9+dx]);
        }
    }
    const float inv = 1.f / 128.f;
    int off = (ty0+ty)*WW + tx0+tx;
    #pragma unroll 1
    for (int d = 0; d < 81; d++)
        cv[(size_t)(b*81 + d)*HW + off] = acc[d] * inv;
}

// ---------------- 1x1 conv (MODE 0: plain read; MODE 1: |inA - inB| on the fly) ----------------
template<int CIN, int COUT, int MODE>
__launch_bounds__(128)
__global__ void conv1x1_k(const float* __restrict__ inA, const float* __restrict__ inB,
                          const float* __restrict__ wgt, float* __restrict__ out)
{
    __shared__ float s_w[COUT*CIN];
    for (int i = threadIdx.x; i < COUT*CIN; i += 128) s_w[i] = wgt[i];
    __syncthreads();
    int p = blockIdx.x*128 + threadIdx.x;
    int b = p / HW, hw = p % HW;
    float acc[COUT];
    #pragma unroll
    for (int co = 0; co < COUT; co++) acc[co] = 0.f;
    #pragma unroll 1
    for (int ci = 0; ci < CIN; ci++) {
        float v;
        if (MODE == 1) {
            size_t idx = (size_t)(b*128 + ci)*HW + hw;
            v = fabsf(inA[idx] - inB[idx]);
        } else {
            v = inA[(size_t)(b*CIN + ci)*HW + hw];
        }
        #pragma unroll
        for (int co = 0; co < COUT; co++)
            acc[co] = fmaf(s_w[co*CIN + ci], v, acc[co]);
    }
    #pragma unroll 1
    for (int co = 0; co < COUT; co++)
        out[(size_t)(b*COUT + co)*HW + hw] = acc[co];
}

// ---------------- effective lam weight: veff[ci] = sum_co lam_w[co] * fus_w2[co][ci] ----------------
__global__ void lam_eff_k(const float* __restrict__ lam_w, const float* __restrict__ fus_w2,
                          float* __restrict__ veff)
{
    int ci = threadIdx.x;
    float a = 0.f;
    for (int co = 0; co < 128; co++)
        a = fmaf(lam_w[co], fus_w2[co*128 + ci], a);
    veff[ci] = a;
}

// ---------------- final: GN(fus)->relu -> dot(veff) -> sigmoid ----------------
__global__ void lam_final_k(const float* __restrict__ fbuf, const float* __restrict__ gamma,
                            const float* __restrict__ beta, const float* __restrict__ mean,
                            const float* __restrict__ rstd, const float* __restrict__ veff,
                            const float* __restrict__ lam_b, float* __restrict__ out_lam)
{
    __shared__ float sg[128], sb[128], sv[128];
    for (int i = threadIdx.x; i < 128; i += blockDim.x) {
        sg[i] = gamma[i]; sb[i] = beta[i]; sv[i] = veff[i];
    }
    __syncthreads();
    int p = blockIdx.x*blockDim.x + threadIdx.x;
    if (p >= BB*HW) return;
    int b = p / HW, hw = p % HW;
    float a = lam_b[0];
    const float* fb = fbuf + (size_t)b*128*HW + hw;
    const float* mp = mean + b*32;
    const float* rp = rstd + b*32;
    #pragma unroll 4
    for (int ci = 0; ci < 128; ci++) {
        float x = fb[(size_t)ci*HW];
        int g = ci >> 2;
        float y = (x - mp[g]) * rp[g] * sg[ci] + sb[ci];
        a = fmaf(fmaxf(y, 0.f), sv[ci], a);
    }
    out_lam[p] = 1.f / (1.f + expf(-a));
}

// ---------------- launch ----------------
extern "C" void kernel_launch(void* const* d_in, const int* in_sizes, int n_in,
                              void* d_out, int out_size)
{
    const float* feat1     = (const float*)d_in[0];
    const float* feat2     = (const float*)d_in[1];
    const float* off_w1    = (const float*)d_in[2];
    const float* off_g1    = (const float*)d_in[3];
    const float* off_b1    = (const float*)d_in[4];
    const float* off_w2    = (const float*)d_in[5];
    const float* off_g2    = (const float*)d_in[6];
    const float* off_b2    = (const float*)d_in[7];
    const float* off_w3    = (const float*)d_in[8];
    const float* off_bias3 = (const float*)d_in[9];
    const float* corr_w    = (const float*)d_in[10];
    const float* corr_g    = (const float*)d_in[11];
    const float* corr_b    = (const float*)d_in[12];
    const float* diff_w    = (const float*)d_in[13];
    const float* diff_g    = (const float*)d_in[14];
    const float* diff_b    = (const float*)d_in[15];
    const float* fus_w1    = (const float*)d_in[16];
    const float* fus_g1    = (const float*)d_in[17];
    const float* fus_b1    = (const float*)d_in[18];
    const float* fus_w2    = (const float*)d_in[19];
    const float* lam_w     = (const float*)d_in[20];
    const float* lam_b     = (const float*)d_in[21];

    float *x1, *x2, *de, *cv, *pred, *valid, *mean, *rstd, *veff;
    cudaGetSymbolAddress((void**)&x1,    g_x1);
    cudaGetSymbolAddress((void**)&x2,    g_x2);
    cudaGetSymbolAddress((void**)&de,    g_de);
    cudaGetSymbolAddress((void**)&cv,    g_cv);
    cudaGetSymbolAddress((void**)&pred,  g_pred);
    cudaGetSymbolAddress((void**)&valid, g_valid);
    cudaGetSymbolAddress((void**)&mean,  g_mean);
    cudaGetSymbolAddress((void**)&rstd,  g_rstd);
    cudaGetSymbolAddress((void**)&veff,  g_veff);

    float* out_aligned = (float*)d_out;
    float* out_flow    = out_aligned + (size_t)BB*128*HW;
    float* out_lam     = out_flow    + (size_t)BB*2*HW;

    float* mean0 = mean;          float* rstd0 = rstd;
    float* mean1 = mean + 256;    float* rstd1 = rstd + 256;
    float* mean2 = mean + 512;    float* rstd2 = rstd + 512;
    float* mean3 = mean + 768;    float* rstd3 = rstd + 768;
    float* mean4 = mean + 1024;   float* rstd4 = rstd + 1024;

    const long BS128 = (long)128*HW;
    const long BS64  = (long)64*HW;

    // offset head: conv1 (concat feat1|feat2) -> GN -> silu
    conv3x3v2_k<256,8><<<dim3(16,BB,16),128>>>(feat1, feat2, BS128, BS128, off_w1, x1, 128);
    gn_stats_k<<<dim3(32,BB),256>>>(x1, mean0, rstd0, 4);
    norm_act_k<0><<<(BB*128*HW/4+255)/256,256>>>(x1, off_g1, off_b1, mean0, rstd0, 128, 4);

    // conv2 -> GN -> silu
    conv3x3v2_k<128,8><<<dim3(16,BB,8),128>>>(x1, x1 + 64*HW, BS128, BS128, off_w2, x2, 64);
    gn_stats_k<<<dim3(32,BB),256>>>(x2, mean1, rstd1, 2);
    norm_act_k<0><<<(BB*64*HW/4+255)/256,256>>>(x2, off_g2, off_b2, mean1, rstd1, 64, 2);

    // conv3 -> pred; flow + validity
    conv3x3v2_k<64,3><<<dim3(16,BB,1),128>>>(x2, x2 + 32*HW, BS64, BS64, off_w3, pred, 3);
    flowval_k<<<(BB*HW+255)/256,256>>>(pred, off_bias3, out_flow, valid);

    // bilinear warp * validity -> aligned (directly into d_out)
    warp_k<<<(BB*HW+255)/256,256>>>(feat2, out_flow, valid, out_aligned);

    // cost volume
    costvol_k<<<dim3(64,BB),256>>>(feat1, out_aligned, cv);

    // corr branch: 1x1(81->64) -> GN -> relu   (ce reuses x2)
    conv1x1_k<81,64,0><<<BB*HW/128,128>>>(cv, nullptr, corr_w, x2);
    gn_stats_k<<<dim3(32,BB),256>>>(x2, mean2, rstd2, 2);
    norm_act_k<1><<<(BB*64*HW/4+255)/256,256>>>(x2, corr_g, corr_b, mean2, rstd2, 64, 2);

    // diff branch: |feat1-aligned| fused into 1x1(128->64) -> GN -> relu
    conv1x1_k<128,64,1><<<BB*HW/128,128>>>(feat1, out_aligned, diff_w, de);
    gn_stats_k<<<dim3(32,BB),256>>>(de, mean3, rstd3, 2);
    norm_act_k<1><<<(BB*64*HW/4+255)/256,256>>>(de, diff_g, diff_b, mean3, rstd3, 64, 2);

    // fusion conv3x3 (concat ce|de) -> GN stats (norm fused into final)
    conv3x3v2_k<128,8><<<dim3(16,BB,16),128>>>(x2, de, BS64, BS64, fus_w1, x1, 128);
    gn_stats_k<<<dim3(32,BB),256>>>(x1, mean4, rstd4, 4);

    // lam: veff = lam_w @ fus_w2, then per-pixel dot + sigmoid
    lam_eff_k<<<1,128>>>(lam_w, fus_w2, veff);
    lam_final_k<<<(BB*HW+255)/256,256>>>(x1, fus_g1, fus_b1, mean4, rstd4, veff, lam_b, out_lam);
}